// round 2
// baseline (speedup 1.0000x reference)
#include <cuda_runtime.h>
#include <math.h>

#define T_LEN 8192
#define NT 512
#define XS 33   // padded row stride for 32-channel shared tiles (conflict-free)

__device__ __forceinline__ float warp_sum(float v) {
    #pragma unroll
    for (int o = 16; o; o >>= 1) v += __shfl_xor_sync(0xffffffffu, v, o);
    return v;
}

__global__ void __launch_bounds__(NT, 1) wavenet_kernel(
    const int*   __restrict__ tokens,
    const float* __restrict__ emb,
    const float* __restrict__ init_w, const float* __restrict__ init_b,
    const float* __restrict__ dil_w,  const float* __restrict__ dil_b,
    const float* __restrict__ filt_w, const float* __restrict__ filt_b,
    const float* __restrict__ gate_w, const float* __restrict__ gate_b,
    const float* __restrict__ res_w,  const float* __restrict__ res_b,
    const float* __restrict__ skip_w, const float* __restrict__ skip_b,
    const float* __restrict__ end1_w, const float* __restrict__ end1_b,
    const float* __restrict__ end2_w, const float* __restrict__ end2_b,
    const float* __restrict__ fc1_w,  const float* __restrict__ fc1_b,
    const float* __restrict__ fc2_w,  const float* __restrict__ fc2_b,
    const float* __restrict__ fc3_w,  const float* __restrict__ fc3_b,
    const float* __restrict__ fc4_w,  const float* __restrict__ fc4_b,
    float* __restrict__ out)
{
    extern __shared__ float sm[];
    float* X   = sm;                 // 77 x XS : current layer input window
    float* RB  = sm + 77*XS;         // 76 x XS : residual (dil-conv output)
    float* GT  = RB + 76*XS;         // 75 x XS : gated = tanh(f)*sig(g)
    float* WD  = GT + 75*XS;         // 64 x XS : dil weights  [rk][c]
    float* WF  = WD + 64*XS;         // 64 x XS : filt weights
    float* WG  = WF + 64*XS;         // 64 x XS : gate weights
    float* WRs = WG + 64*XS;         // 32 x XS : res weights [r][c]
    float* BS  = WRs + 32*XS;        // 128     : biases (dil,filt,gate,res)
    __shared__ int stok[77];

    const int b    = blockIdx.x;
    const int tid  = threadIdx.x;
    const int lane = tid & 31;
    const int warp = tid >> 5;

    // ================= embedding + init 1x1 conv over 77-wide cone ========
    if (tid < 77) stok[tid] = tokens[b * T_LEN + (T_LEN - 77) + tid];
    float* WI = RB + 77*101;          // init_w^T: [e][c], stride XS (overlay)
    for (int t = tid; t < 32*100; t += NT)
        WI[(t % 100) * XS + (t / 100)] = init_w[t];
    __syncthreads();
    float* SE = RB;                   // emb rows: [p][e], stride 101 (overlay)
    for (int t = tid; t < 77*100; t += NT) {
        int p = t / 100, e = t - p * 100;
        SE[p*101 + e] = emb[stok[p]*100 + e];
    }
    __syncthreads();
    {
        const int cg = warp & 7, pg = warp >> 3;
        const int cb = cg * 4;
        int u0 = lane + 32*pg;
        int u1 = lane + 64 + 32*pg;
        bool v0 = (u0 < 77), v1 = (u1 < 77);
        int uu0 = v0 ? u0 : 0, uu1 = v1 ? u1 : 0;
        float a0[4], a1[4];
        #pragma unroll
        for (int j = 0; j < 4; j++) {
            float bb = __ldg(&init_b[cb + j]);
            a0[j] = bb; a1[j] = bb;
        }
        #pragma unroll 4
        for (int e = 0; e < 100; e++) {
            float ea = SE[uu0*101 + e];
            float eb = SE[uu1*101 + e];
            #pragma unroll
            for (int j = 0; j < 4; j++) {
                float w = WI[e*XS + cb + j];
                a0[j] += w * ea;
                a1[j] += w * eb;
            }
        }
        if (v0) {
            #pragma unroll
            for (int j = 0; j < 4; j++) X[u0*XS + cb + j] = a0[j];
        }
        if (v1) {
            #pragma unroll
            for (int j = 0; j < 4; j++) X[u1*XS + cb + j] = a1[j];
        }
    }
    __syncthreads();

    // ================= 16 dilated layers over shrinking windows ===========
    int W = 75;  // output window width of layer 0
    #pragma unroll 1
    for (int li = 0; li < 16; li++) {
        const int d = 1 << (li & 3);
        if (li) W -= d + 1;

        // ---- stage this layer's weights/biases into shared ----
        const float* gd = dil_w  + li*2048;
        const float* gf = filt_w + li*2048;
        const float* gg = gate_w + li*2048;
        for (int t = tid; t < 2048; t += NT) {
            int c = t >> 6, rk = t & 63;    // global layout [c][r][k]
            WD[rk*XS + c] = gd[t];
            WF[rk*XS + c] = gf[t];
            WG[rk*XS + c] = gg[t];
        }
        const float* gr = res_w + li*1024;
        for (int t = tid; t < 1024; t += NT)
            WRs[(t & 31)*XS + (t >> 5)] = gr[t];
        if (tid < 32) {
            BS[tid]      = dil_b [li*32 + tid];
            BS[32 + tid] = filt_b[li*32 + tid];
            BS[64 + tid] = gate_b[li*32 + tid];
            BS[96 + tid] = res_b [li*32 + tid];
        }
        __syncthreads();

        // ---- residual = dilated conv (2 taps), u in [0, W] ----
        {
            const int cg = warp & 7, pg = warp >> 3;
            const int cb = cg * 4;
            int u0 = lane + 32*pg;
            int u1 = lane + 64 + 32*pg;
            bool v0 = (u0 <= W), v1 = (u1 <= W);
            int uu0 = v0 ? u0 : 0, uu1 = v1 ? u1 : 0;
            float a0[4], a1[4];
            #pragma unroll
            for (int j = 0; j < 4; j++) { a0[j] = BS[cb + j]; a1[j] = a0[j]; }
            #pragma unroll 4
            for (int r = 0; r < 32; r++) {
                float xa0 = X[uu0*XS + r], xb0 = X[(uu0 + d)*XS + r];
                float xa1 = X[uu1*XS + r], xb1 = X[(uu1 + d)*XS + r];
                #pragma unroll
                for (int j = 0; j < 4; j++) {
                    float w0 = WD[(2*r    )*XS + cb + j];
                    float w1 = WD[(2*r + 1)*XS + cb + j];
                    a0[j] += w0*xa0 + w1*xb0;
                    a1[j] += w0*xa1 + w1*xb1;
                }
            }
            if (v0) {
                #pragma unroll
                for (int j = 0; j < 4; j++) RB[u0*XS + cb + j] = a0[j];
            }
            if (v1) {
                #pragma unroll
                for (int j = 0; j < 4; j++) RB[u1*XS + cb + j] = a1[j];
            }
        }
        __syncthreads();

        // ---- filter & gate convs (2 taps) + gated product, u in [0, W) ----
        if (warp < 8) {
            const int cb = warp * 4;
            float af[3][4], ag[3][4];
            #pragma unroll
            for (int p = 0; p < 3; p++)
                #pragma unroll
                for (int j = 0; j < 4; j++) {
                    af[p][j] = BS[32 + cb + j];
                    ag[p][j] = BS[64 + cb + j];
                }
            int u[3], uu[3]; bool v[3];
            #pragma unroll
            for (int p = 0; p < 3; p++) {
                u[p] = lane + 32*p; v[p] = (u[p] < W); uu[p] = v[p] ? u[p] : 0;
            }
            #pragma unroll 2
            for (int r = 0; r < 32; r++) {
                float ra[3], rb[3];
                #pragma unroll
                for (int p = 0; p < 3; p++) {
                    ra[p] = RB[ uu[p]     *XS + r];
                    rb[p] = RB[(uu[p] + 1)*XS + r];
                }
                #pragma unroll
                for (int j = 0; j < 4; j++) {
                    float f0 = WF[(2*r)*XS + cb + j], f1 = WF[(2*r+1)*XS + cb + j];
                    float g0 = WG[(2*r)*XS + cb + j], g1 = WG[(2*r+1)*XS + cb + j];
                    #pragma unroll
                    for (int p = 0; p < 3; p++) {
                        af[p][j] += f0*ra[p] + f1*rb[p];
                        ag[p][j] += g0*ra[p] + g1*rb[p];
                    }
                }
            }
            #pragma unroll
            for (int p = 0; p < 3; p++) if (v[p]) {
                #pragma unroll
                for (int j = 0; j < 4; j++) {
                    float tf = tanhf(af[p][j]);
                    float sg = 1.0f / (1.0f + expf(-ag[p][j]));
                    GT[u[p]*XS + cb + j] = tf * sg;
                }
            }
        }
        __syncthreads();

        // ---- res 1x1 conv + residual add -> new X, u in [0, W) ----
        if (li < 15) {
            const int cg = warp & 7, pg = warp >> 3;
            const int cb = cg * 4;
            int u0 = lane + 32*pg;
            int u1 = lane + 64 + 32*pg;
            bool v0 = (u0 < W), v1 = (u1 < W);
            int uu0 = v0 ? u0 : 0, uu1 = v1 ? u1 : 0;
            float a0[4], a1[4];
            #pragma unroll
            for (int j = 0; j < 4; j++) { a0[j] = BS[96 + cb + j]; a1[j] = a0[j]; }
            #pragma unroll 4
            for (int r = 0; r < 32; r++) {
                float g0 = GT[uu0*XS + r];
                float g1 = GT[uu1*XS + r];
                #pragma unroll
                for (int j = 0; j < 4; j++) {
                    float w = WRs[r*XS + cb + j];
                    a0[j] += w * g0;
                    a1[j] += w * g1;
                }
            }
            if (v0) {
                #pragma unroll
                for (int j = 0; j < 4; j++)
                    X[u0*XS + cb + j] = a0[j] + RB[u0*XS + cb + j];
            }
            if (v1) {
                #pragma unroll
                for (int j = 0; j < 4; j++)
                    X[u1*XS + cb + j] = a1[j] + RB[u1*XS + cb + j];
            }
            __syncthreads();
        }
    }

    // ================= tail: skip/end/fc at t = T-1 only =================
    // GT[0..31] (row 0) holds the layer-15 gated output at t = T-1.
    float* SV = RB;        // relu(skip) 256
    float* H1 = RB + 256;  // 256
    float* H2 = RB + 512;  // 256
    float* F1 = RB + 768;  // 128
    float* F2 = RB + 896;  // 128
    float* F3 = RB + 1024; // 64

    const float* skw = skip_w + 15*256*32;
    const float* skb = skip_b + 15*256;
    float gv = GT[lane];
    for (int o = warp; o < 256; o += 16) {
        float v = skw[o*32 + lane] * gv;
        v = warp_sum(v);
        if (lane == 0) SV[o] = fmaxf(v + skb[o], 0.f);
    }
    __syncthreads();
    for (int o = warp; o < 256; o += 16) {
        float v = 0.f;
        #pragma unroll
        for (int q = 0; q < 8; q++) { int s = q*32 + lane; v += end1_w[o*256 + s] * SV[s]; }
        v = warp_sum(v);
        if (lane == 0) H1[o] = fmaxf(v + end1_b[o], 0.f);
    }
    __syncthreads();
    for (int o = warp; o < 256; o += 16) {
        float v = 0.f;
        #pragma unroll
        for (int q = 0; q < 8; q++) { int s = q*32 + lane; v += end2_w[o*256 + s] * H1[s]; }
        v = warp_sum(v);
        if (lane == 0) H2[o] = v + end2_b[o];
    }
    __syncthreads();
    for (int o = warp; o < 128; o += 16) {
        float v = 0.f;
        #pragma unroll
        for (int q = 0; q < 8; q++) { int s = q*32 + lane; v += fc1_w[o*256 + s] * H2[s]; }
        v = warp_sum(v);
        if (lane == 0) F1[o] = fmaxf(v + fc1_b[o], 0.f);
    }
    __syncthreads();
    for (int o = warp; o < 128; o += 16) {
        float v = 0.f;
        #pragma unroll
        for (int q = 0; q < 4; q++) { int s = q*32 + lane; v += fc2_w[o*128 + s] * F1[s]; }
        v = warp_sum(v);
        if (lane == 0) F2[o] = fmaxf(v + fc2_b[o], 0.f);
    }
    __syncthreads();
    for (int o = warp; o < 64; o += 16) {
        float v = 0.f;
        #pragma unroll
        for (int q = 0; q < 4; q++) { int s = q*32 + lane; v += fc3_w[o*128 + s] * F2[s]; }
        v = warp_sum(v);
        if (lane == 0) F3[o] = fmaxf(v + fc3_b[o], 0.f);
    }
    __syncthreads();
    for (int o = warp; o < 256; o += 16) {
        float v = 0.f;
        #pragma unroll
        for (int q = 0; q < 2; q++) { int s = q*32 + lane; v += fc4_w[o*64 + s] * F3[s]; }
        v = warp_sum(v);
        if (lane == 0) out[b*256 + o] = v + fc4_b[o];
    }
}

extern "C" void kernel_launch(void* const* d_in, const int* in_sizes, int n_in,
                              void* d_out, int out_size)
{
    (void)in_sizes; (void)n_in; (void)out_size;
    const size_t smem_bytes = (size_t)(77*XS + 76*XS + 75*XS + 3*64*XS + 32*XS + 128) * sizeof(float);
    cudaFuncSetAttribute(wavenet_kernel, cudaFuncAttributeMaxDynamicSharedMemorySize,
                         (int)smem_bytes);
    wavenet_kernel<<<16, NT, smem_bytes>>>(
        (const int*)  d_in[0],  (const float*)d_in[1],
        (const float*)d_in[2],  (const float*)d_in[3],
        (const float*)d_in[4],  (const float*)d_in[5],
        (const float*)d_in[6],  (const float*)d_in[7],
        (const float*)d_in[8],  (const float*)d_in[9],
        (const float*)d_in[10], (const float*)d_in[11],
        (const float*)d_in[12], (const float*)d_in[13],
        (const float*)d_in[14], (const float*)d_in[15],
        (const float*)d_in[16], (const float*)d_in[17],
        (const float*)d_in[18], (const float*)d_in[19],
        (const float*)d_in[20], (const float*)d_in[21],
        (const float*)d_in[22], (const float*)d_in[23],
        (const float*)d_in[24], (const float*)d_in[25],
        (float*)d_out);
}

// round 4
// speedup vs baseline: 1.4018x; 1.4018x over previous
#include <cuda_runtime.h>
#include <math.h>

#define T_LEN 8192
#define NT 512
#define XS 36    // padded row stride: %4==0 for LDS.128 alignment, 4u-bank-rotation conflict-free
#define SESTR 104

typedef unsigned long long u64;

__device__ __forceinline__ u64 pack2(float lo, float hi) {
    u64 r; asm("mov.b64 %0,{%1,%2};" : "=l"(r) : "f"(lo), "f"(hi)); return r;
}
__device__ __forceinline__ u64 dup2(float x) { return pack2(x, x); }
__device__ __forceinline__ void fma2(u64& a, u64 w, u64 x) {
    asm("fma.rn.f32x2 %0,%1,%2,%0;" : "+l"(a) : "l"(w), "l"(x));
}
__device__ __forceinline__ u64 add2(u64 a, u64 b) {
    u64 r; asm("add.rn.f32x2 %0,%1,%2;" : "=l"(r) : "l"(a), "l"(b)); return r;
}
__device__ __forceinline__ float2 unpk(u64 a) {
    float2 f; asm("mov.b64 {%0,%1},%2;" : "=f"(f.x), "=f"(f.y) : "l"(a)); return f;
}
__device__ __forceinline__ float warp_sum(float v) {
    #pragma unroll
    for (int o = 16; o; o >>= 1) v += __shfl_xor_sync(0xffffffffu, v, o);
    return v;
}
__device__ __forceinline__ float fast_tanh(float x) {
    // tanh(x) = 2/(1+exp(-2x)) - 1
    float e = __expf(-2.0f * x);
    return fmaf(2.0f, __frcp_rn(1.0f + e), -1.0f);
}
__device__ __forceinline__ float fast_sig(float x) {
    return __frcp_rn(1.0f + __expf(-x));
}

__global__ void __launch_bounds__(NT, 1) wavenet_kernel(
    const int*   __restrict__ tokens,
    const float* __restrict__ emb,
    const float* __restrict__ init_w, const float* __restrict__ init_b,
    const float* __restrict__ dil_w,  const float* __restrict__ dil_b,
    const float* __restrict__ filt_w, const float* __restrict__ filt_b,
    const float* __restrict__ gate_w, const float* __restrict__ gate_b,
    const float* __restrict__ res_w,  const float* __restrict__ res_b,
    const float* __restrict__ skip_w, const float* __restrict__ skip_b,
    const float* __restrict__ end1_w, const float* __restrict__ end1_b,
    const float* __restrict__ end2_w, const float* __restrict__ end2_b,
    const float* __restrict__ fc1_w,  const float* __restrict__ fc1_b,
    const float* __restrict__ fc2_w,  const float* __restrict__ fc2_b,
    const float* __restrict__ fc3_w,  const float* __restrict__ fc3_b,
    const float* __restrict__ fc4_w,  const float* __restrict__ fc4_b,
    float* __restrict__ out)
{
    extern __shared__ float sm[];
    float* X   = sm;                  // 77 x XS
    float* RB  = sm + 77*XS;          // 76 x XS
    float* GT  = RB + 76*XS;          // 75 x XS (activated gated output)
    float* WD  = GT + 75*XS;          // 64 x XS [rk][c]
    float* WF  = WD + 64*XS;          // 64 x XS
    float* WG  = WF + 64*XS;          // 64 x XS
    float* WRs = WG + 64*XS;          // 32 x XS [r][c]
    float* BS  = WRs + 32*XS;         // 128 biases
    __shared__ int stok[77];

    const int b    = blockIdx.x;
    const int tid  = threadIdx.x;
    const int lane = tid & 31;
    const int warp = tid >> 5;
    const int cg   = warp & 3;        // 4 channel groups of 8
    const int pg   = warp >> 2;       // 4 position groups of 32
    const int cb   = cg * 8;
    const int u    = lane + 32 * pg;

    // ================= embedding + init 1x1 conv (77-wide cone) ===========
    if (tid < 77) stok[tid] = tokens[b * T_LEN + (T_LEN - 77) + tid];
    float* SE = RB;                   // [p][e] stride SESTR (overlay, 77*104=8008)
    float* WI = RB + 77*SESTR;        // [e][c] stride XS (3600 floats)
    for (int t = tid; t < 32*100; t += NT)
        WI[(t % 100) * XS + (t / 100)] = init_w[t];
    __syncthreads();
    for (int t = tid; t < 77*100; t += NT) {
        int p = t / 100, e = t - p * 100;
        SE[p*SESTR + e] = emb[stok[p]*100 + e];
    }
    __syncthreads();
    if (u < 77) {
        u64 a0 = pack2(init_b[cb],   init_b[cb+1]);
        u64 a1 = pack2(init_b[cb+2], init_b[cb+3]);
        u64 a2 = pack2(init_b[cb+4], init_b[cb+5]);
        u64 a3 = pack2(init_b[cb+6], init_b[cb+7]);
        const float* xr = &SE[u*SESTR];
        #pragma unroll 4
        for (int e = 0; e < 100; e += 4) {
            float4 xv = *(const float4*)(xr + e);
            #pragma unroll
            for (int ee = 0; ee < 4; ee++) {
                u64 d0 = dup2((&xv.x)[ee]);
                const float* w = &WI[(e + ee)*XS + cb];
                ulonglong2 Wa = *(const ulonglong2*)w;
                ulonglong2 Wb = *(const ulonglong2*)(w + 4);
                fma2(a0, Wa.x, d0); fma2(a1, Wa.y, d0);
                fma2(a2, Wb.x, d0); fma2(a3, Wb.y, d0);
            }
        }
        ulonglong2 s0; s0.x = a0; s0.y = a1;
        ulonglong2 s1; s1.x = a2; s1.y = a3;
        *(ulonglong2*)&X[u*XS + cb]     = s0;
        *(ulonglong2*)&X[u*XS + cb + 4] = s1;
    }
    __syncthreads();

    // ================= 16 dilated layers =================================
    int W = 75;
    #pragma unroll 1
    for (int li = 0; li < 16; li++) {
        const int d = 1 << (li & 3);
        if (li) W -= d + 1;

        // ---- stage weights/biases ----
        const float* gd = dil_w  + li*2048;
        const float* gf = filt_w + li*2048;
        const float* gg = gate_w + li*2048;
        for (int t = tid; t < 2048; t += NT) {
            int c = t >> 6, rk = t & 63;
            WD[rk*XS + c] = gd[t];
            WF[rk*XS + c] = gf[t];
            WG[rk*XS + c] = gg[t];
        }
        const float* gr = res_w + li*1024;
        for (int t = tid; t < 1024; t += NT)
            WRs[(t & 31)*XS + (t >> 5)] = gr[t];
        if (tid < 32) {
            BS[tid]      = dil_b [li*32 + tid];
            BS[32 + tid] = filt_b[li*32 + tid];
            BS[64 + tid] = gate_b[li*32 + tid];
            BS[96 + tid] = res_b [li*32 + tid];
        }
        __syncthreads();

        // ---- residual = dilated conv (2 taps), u in [0, W] ----
        if (u <= W) {
            u64 a0 = pack2(BS[cb],   BS[cb+1]);
            u64 a1 = pack2(BS[cb+2], BS[cb+3]);
            u64 a2 = pack2(BS[cb+4], BS[cb+5]);
            u64 a3 = pack2(BS[cb+6], BS[cb+7]);
            const float* xr0 = &X[u*XS];
            const float* xr1 = &X[(u + d)*XS];
            #pragma unroll
            for (int r = 0; r < 32; r += 4) {
                float4 xa = *(const float4*)(xr0 + r);
                float4 xb = *(const float4*)(xr1 + r);
                #pragma unroll
                for (int rr = 0; rr < 4; rr++) {
                    u64 da = dup2((&xa.x)[rr]);
                    u64 db = dup2((&xb.x)[rr]);
                    const float* w0 = &WD[(2*(r + rr))*XS + cb];
                    ulonglong2 W0a = *(const ulonglong2*)w0;
                    ulonglong2 W0b = *(const ulonglong2*)(w0 + 4);
                    ulonglong2 W1a = *(const ulonglong2*)(w0 + XS);
                    ulonglong2 W1b = *(const ulonglong2*)(w0 + XS + 4);
                    fma2(a0, W0a.x, da); fma2(a1, W0a.y, da);
                    fma2(a2, W0b.x, da); fma2(a3, W0b.y, da);
                    fma2(a0, W1a.x, db); fma2(a1, W1a.y, db);
                    fma2(a2, W1b.x, db); fma2(a3, W1b.y, db);
                }
            }
            ulonglong2 s0; s0.x = a0; s0.y = a1;
            ulonglong2 s1; s1.x = a2; s1.y = a3;
            *(ulonglong2*)&RB[u*XS + cb]     = s0;
            *(ulonglong2*)&RB[u*XS + cb + 4] = s1;
        }
        __syncthreads();

        // ---- filter & gate convs + activation + product, u in [0, W) ----
        if (u < W) {
            u64 f0 = pack2(BS[32+cb],   BS[32+cb+1]);
            u64 f1 = pack2(BS[32+cb+2], BS[32+cb+3]);
            u64 f2 = pack2(BS[32+cb+4], BS[32+cb+5]);
            u64 f3 = pack2(BS[32+cb+6], BS[32+cb+7]);
            u64 g0 = pack2(BS[64+cb],   BS[64+cb+1]);
            u64 g1 = pack2(BS[64+cb+2], BS[64+cb+3]);
            u64 g2 = pack2(BS[64+cb+4], BS[64+cb+5]);
            u64 g3 = pack2(BS[64+cb+6], BS[64+cb+7]);
            const float* rr0 = &RB[u*XS];
            const float* rr1 = &RB[(u + 1)*XS];
            #pragma unroll
            for (int r = 0; r < 32; r += 4) {
                float4 xa = *(const float4*)(rr0 + r);
                float4 xb = *(const float4*)(rr1 + r);
                #pragma unroll
                for (int rr = 0; rr < 4; rr++) {
                    u64 da = dup2((&xa.x)[rr]);
                    u64 db = dup2((&xb.x)[rr]);
                    const float* wf0 = &WF[(2*(r + rr))*XS + cb];
                    ulonglong2 F0a = *(const ulonglong2*)wf0;
                    ulonglong2 F0b = *(const ulonglong2*)(wf0 + 4);
                    ulonglong2 F1a = *(const ulonglong2*)(wf0 + XS);
                    ulonglong2 F1b = *(const ulonglong2*)(wf0 + XS + 4);
                    fma2(f0, F0a.x, da); fma2(f1, F0a.y, da);
                    fma2(f2, F0b.x, da); fma2(f3, F0b.y, da);
                    fma2(f0, F1a.x, db); fma2(f1, F1a.y, db);
                    fma2(f2, F1b.x, db); fma2(f3, F1b.y, db);
                    const float* wg0 = &WG[(2*(r + rr))*XS + cb];
                    ulonglong2 G0a = *(const ulonglong2*)wg0;
                    ulonglong2 G0b = *(const ulonglong2*)(wg0 + 4);
                    ulonglong2 G1a = *(const ulonglong2*)(wg0 + XS);
                    ulonglong2 G1b = *(const ulonglong2*)(wg0 + XS + 4);
                    fma2(g0, G0a.x, da); fma2(g1, G0a.y, da);
                    fma2(g2, G0b.x, da); fma2(g3, G0b.y, da);
                    fma2(g0, G1a.x, db); fma2(g1, G1a.y, db);
                    fma2(g2, G1b.x, db); fma2(g3, G1b.y, db);
                }
            }
            float2 Fv[4] = {unpk(f0), unpk(f1), unpk(f2), unpk(f3)};
            float2 Gv[4] = {unpk(g0), unpk(g1), unpk(g2), unpk(g3)};
            float o[8];
            #pragma unroll
            for (int k = 0; k < 4; k++) {
                o[2*k]   = fast_tanh(Fv[k].x) * fast_sig(Gv[k].x);
                o[2*k+1] = fast_tanh(Fv[k].y) * fast_sig(Gv[k].y);
            }
            *(float4*)&GT[u*XS + cb]     = make_float4(o[0], o[1], o[2], o[3]);
            *(float4*)&GT[u*XS + cb + 4] = make_float4(o[4], o[5], o[6], o[7]);
        }
        __syncthreads();

        // ---- res 1x1 conv + residual add -> new X, u in [0, W) ----
        if (li < 15) {
            if (u < W) {
                u64 a0 = pack2(BS[96+cb],   BS[96+cb+1]);
                u64 a1 = pack2(BS[96+cb+2], BS[96+cb+3]);
                u64 a2 = pack2(BS[96+cb+4], BS[96+cb+5]);
                u64 a3 = pack2(BS[96+cb+6], BS[96+cb+7]);
                const float* gr0 = &GT[u*XS];
                #pragma unroll
                for (int r = 0; r < 32; r += 4) {
                    float4 xa = *(const float4*)(gr0 + r);
                    #pragma unroll
                    for (int rr = 0; rr < 4; rr++) {
                        u64 da = dup2((&xa.x)[rr]);
                        const float* w = &WRs[(r + rr)*XS + cb];
                        ulonglong2 Wa = *(const ulonglong2*)w;
                        ulonglong2 Wb = *(const ulonglong2*)(w + 4);
                        fma2(a0, Wa.x, da); fma2(a1, Wa.y, da);
                        fma2(a2, Wb.x, da); fma2(a3, Wb.y, da);
                    }
                }
                ulonglong2 rv0 = *(const ulonglong2*)&RB[u*XS + cb];
                ulonglong2 rv1 = *(const ulonglong2*)&RB[u*XS + cb + 4];
                ulonglong2 s0; s0.x = add2(a0, rv0.x); s0.y = add2(a1, rv0.y);
                ulonglong2 s1; s1.x = add2(a2, rv1.x); s1.y = add2(a3, rv1.y);
                *(ulonglong2*)&X[u*XS + cb]     = s0;
                *(ulonglong2*)&X[u*XS + cb + 4] = s1;
            }
            __syncthreads();
        }
    }

    // ================= tail: skip/end/fc at t = T-1 only =================
    float* SV = RB;        // relu(skip) 256
    float* H1 = RB + 256;  // 256
    float* H2 = RB + 512;  // 256
    float* F1 = RB + 768;  // 128
    float* F2 = RB + 896;  // 128
    float* F3 = RB + 1024; // 64

    const float* skw = skip_w + 15*256*32;
    const float* skb = skip_b + 15*256;
    float gv = GT[lane];
    for (int o = warp; o < 256; o += 16) {
        float v = skw[o*32 + lane] * gv;
        v = warp_sum(v);
        if (lane == 0) SV[o] = fmaxf(v + skb[o], 0.f);
    }
    __syncthreads();
    for (int o = warp; o < 256; o += 16) {
        float v = 0.f;
        #pragma unroll
        for (int q = 0; q < 8; q++) { int s = q*32 + lane; v += end1_w[o*256 + s] * SV[s]; }
        v = warp_sum(v);
        if (lane == 0) H1[o] = fmaxf(v + end1_b[o], 0.f);
    }
    __syncthreads();
    for (int o = warp; o < 256; o += 16) {
        float v = 0.f;
        #pragma unroll
        for (int q = 0; q < 8; q++) { int s = q*32 + lane; v += end2_w[o*256 + s] * H1[s]; }
        v = warp_sum(v);
        if (lane == 0) H2[o] = v + end2_b[o];
    }
    __syncthreads();
    for (int o = warp; o < 128; o += 16) {
        float v = 0.f;
        #pragma unroll
        for (int q = 0; q < 8; q++) { int s = q*32 + lane; v += fc1_w[o*256 + s] * H2[s]; }
        v = warp_sum(v);
        if (lane == 0) F1[o] = fmaxf(v + fc1_b[o], 0.f);
    }
    __syncthreads();
    for (int o = warp; o < 128; o += 16) {
        float v = 0.f;
        #pragma unroll
        for (int q = 0; q < 4; q++) { int s = q*32 + lane; v += fc2_w[o*128 + s] * F1[s]; }
        v = warp_sum(v);
        if (lane == 0) F2[o] = fmaxf(v + fc2_b[o], 0.f);
    }
    __syncthreads();
    for (int o = warp; o < 64; o += 16) {
        float v = 0.f;
        #pragma unroll
        for (int q = 0; q < 4; q++) { int s = q*32 + lane; v += fc3_w[o*128 + s] * F2[s]; }
        v = warp_sum(v);
        if (lane == 0) F3[o] = fmaxf(v + fc3_b[o], 0.f);
    }
    __syncthreads();
    for (int o = warp; o < 256; o += 16) {
        float v = 0.f;
        #pragma unroll
        for (int q = 0; q < 2; q++) { int s = q*32 + lane; v += fc4_w[o*64 + s] * F3[s]; }
        v = warp_sum(v);
        if (lane == 0) out[b*256 + o] = v + fc4_b[o];
    }
}

extern "C" void kernel_launch(void* const* d_in, const int* in_sizes, int n_in,
                              void* d_out, int out_size)
{
    (void)in_sizes; (void)n_in; (void)out_size;
    const size_t smem_bytes = (size_t)(77*XS + 76*XS + 75*XS + 3*64*XS + 32*XS + 128) * sizeof(float);
    cudaFuncSetAttribute(wavenet_kernel, cudaFuncAttributeMaxDynamicSharedMemorySize,
                         (int)smem_bytes);
    wavenet_kernel<<<16, NT, smem_bytes>>>(
        (const int*)  d_in[0],  (const float*)d_in[1],
        (const float*)d_in[2],  (const float*)d_in[3],
        (const float*)d_in[4],  (const float*)d_in[5],
        (const float*)d_in[6],  (const float*)d_in[7],
        (const float*)d_in[8],  (const float*)d_in[9],
        (const float*)d_in[10], (const float*)d_in[11],
        (const float*)d_in[12], (const float*)d_in[13],
        (const float*)d_in[14], (const float*)d_in[15],
        (const float*)d_in[16], (const float*)d_in[17],
        (const float*)d_in[18], (const float*)d_in[19],
        (const float*)d_in[20], (const float*)d_in[21],
        (const float*)d_in[22], (const float*)d_in[23],
        (const float*)d_in[24], (const float*)d_in[25],
        (float*)d_out);
}

// round 5
// speedup vs baseline: 1.4662x; 1.0459x over previous
#include <cuda_runtime.h>
#include <math.h>

#define T_LEN 8192
#define NT 512
#define XS 36          // padded row stride: 16B-aligned, phase-conflict-free (4-word rotation)
#define SESTR 104

// float offsets in dynamic smem
#define OFF_X   0          // 77 x XS
#define OFF_RB  2772       // 76 x XS
#define OFF_GT  5508       // 75 x XS
#define OFF_WB  8208       // 3 weight buffers of WBSZ
#define WBSZ    8192
// inside a weight buffer
#define WDO 0              // 64 x XS
#define WFO 2304
#define WGO 4608
#define WRO 6912           // 32 x XS
#define BSO 8064           // 128 biases
#define SMEM_FLOATS (OFF_WB + 3*WBSZ)   // 32784 floats = 131136 B

typedef unsigned long long u64;

__device__ __forceinline__ u64 pack2(float lo, float hi) {
    u64 r; asm("mov.b64 %0,{%1,%2};" : "=l"(r) : "f"(lo), "f"(hi)); return r;
}
__device__ __forceinline__ u64 dup2(float x) { return pack2(x, x); }
__device__ __forceinline__ void fma2(u64& a, u64 w, u64 x) {
    asm("fma.rn.f32x2 %0,%1,%2,%0;" : "+l"(a) : "l"(w), "l"(x));
}
__device__ __forceinline__ u64 add2(u64 a, u64 b) {
    u64 r; asm("add.rn.f32x2 %0,%1,%2;" : "=l"(r) : "l"(a), "l"(b)); return r;
}
__device__ __forceinline__ float2 unpk(u64 a) {
    float2 f; asm("mov.b64 {%0,%1},%2;" : "=f"(f.x), "=f"(f.y) : "l"(a)); return f;
}
__device__ __forceinline__ float warp_sum(float v) {
    #pragma unroll
    for (int o = 16; o; o >>= 1) v += __shfl_xor_sync(0xffffffffu, v, o);
    return v;
}
__device__ __forceinline__ float fast_tanh(float x) {
    float e = __expf(-2.0f * x);
    return fmaf(2.0f, __frcp_rn(1.0f + e), -1.0f);
}
__device__ __forceinline__ float fast_sig(float x) {
    return __frcp_rn(1.0f + __expf(-x));
}
__device__ __forceinline__ float dot4(float4 a, float4 b) {
    return fmaf(a.x, b.x, fmaf(a.y, b.y, fmaf(a.z, b.z, a.w * b.w)));
}

__global__ void __launch_bounds__(NT, 1) wavenet_kernel(
    const int*   __restrict__ tokens,
    const float* __restrict__ emb,
    const float* __restrict__ init_w, const float* __restrict__ init_b,
    const float* __restrict__ dil_w,  const float* __restrict__ dil_b,
    const float* __restrict__ filt_w, const float* __restrict__ filt_b,
    const float* __restrict__ gate_w, const float* __restrict__ gate_b,
    const float* __restrict__ res_w,  const float* __restrict__ res_b,
    const float* __restrict__ skip_w, const float* __restrict__ skip_b,
    const float* __restrict__ end1_w, const float* __restrict__ end1_b,
    const float* __restrict__ end2_w, const float* __restrict__ end2_b,
    const float* __restrict__ fc1_w,  const float* __restrict__ fc1_b,
    const float* __restrict__ fc2_w,  const float* __restrict__ fc2_b,
    const float* __restrict__ fc3_w,  const float* __restrict__ fc3_b,
    const float* __restrict__ fc4_w,  const float* __restrict__ fc4_b,
    float* __restrict__ out)
{
    extern __shared__ float sm[];
    __shared__ int stok[77];

    float* X  = sm + OFF_X;
    float* RB = sm + OFF_RB;
    float* GT = sm + OFF_GT;

    const int b    = blockIdx.x;
    const int tid  = threadIdx.x;
    const int lane = tid & 31;
    const int warp = tid >> 5;
    const int cg   = warp & 3;          // 4 channel groups of 8 (compute warps)
    const int pg   = (warp >> 2) & 1;   // 2 position groups
    const int cb   = cg * 8;
    const int u0   = lane + 64 * pg;
    const int u1   = u0 + 32;
    const int s    = tid - 256;         // staging thread id (warps 8-15)

    // ---- staging helper: layer li -> weight buffer bi (threads 256..511) ----
    auto stage = [&](int li, int bi) {
        float* B = sm + OFF_WB + bi * WBSZ;
        const float* gd = dil_w  + li * 2048;
        const float* gf = filt_w + li * 2048;
        const float* gg = gate_w + li * 2048;
        const float* gr = res_w  + li * 1024;
        #pragma unroll
        for (int k = 0; k < 8; k++) {
            int t = s + 256 * k;
            int c = t >> 6, rk = t & 63;
            int o = rk * XS + c;
            B[WDO + o] = __ldg(gd + t);
            B[WFO + o] = __ldg(gf + t);
            B[WGO + o] = __ldg(gg + t);
        }
        #pragma unroll
        for (int k = 0; k < 4; k++) {
            int t = s + 256 * k;
            B[WRO + (t & 31) * XS + (t >> 5)] = __ldg(gr + t);
        }
        if (s < 128) {
            int q = s >> 5, i = s & 31;
            const float* bp = (q == 0) ? dil_b : (q == 1) ? filt_b : (q == 2) ? gate_b : res_b;
            B[BSO + s] = __ldg(bp + li * 32 + i);
        }
    };

    // ================= init: split work between warp groups ===============
    if (warp < 8) {
        // embedding gather + init 1x1 conv over the 77-wide cone
        if (tid < 77) stok[tid] = tokens[b * T_LEN + (T_LEN - 77) + tid];
        float* WI = RB;                      // [e][c] stride XS (3600 fl, fits RB+GT)
        for (int t = tid; t < 3200; t += 256)
            WI[(t % 100) * XS + (t / 100)] = init_w[t];
        asm volatile("bar.sync 1, 256;");
        float* SE = sm + OFF_WB + 2 * WBSZ;  // [p][e] stride SESTR in buf2 (8008 fl)
        for (int t = tid; t < 7700; t += 256) {
            int p = t / 100, e = t - p * 100;
            SE[p * SESTR + e] = emb[stok[p] * 100 + e];
        }
        asm volatile("bar.sync 1, 256;");
        {
            const int v0 = (u0 < 77), v1 = (u1 < 77);
            const int uu0 = v0 ? u0 : 0, uu1 = v1 ? u1 : 0;
            u64 a0 = pack2(init_b[cb],   init_b[cb+1]);
            u64 a1 = pack2(init_b[cb+2], init_b[cb+3]);
            u64 a2 = pack2(init_b[cb+4], init_b[cb+5]);
            u64 a3 = pack2(init_b[cb+6], init_b[cb+7]);
            u64 b0 = a0, b1 = a1, b2 = a2, b3 = a3;
            const float* xr0 = &SE[uu0 * SESTR];
            const float* xr1 = &SE[uu1 * SESTR];
            #pragma unroll 4
            for (int e = 0; e < 100; e += 4) {
                float4 x0 = *(const float4*)(xr0 + e);
                float4 x1 = *(const float4*)(xr1 + e);
                #pragma unroll
                for (int ee = 0; ee < 4; ee++) {
                    u64 d0 = dup2((&x0.x)[ee]);
                    u64 d1 = dup2((&x1.x)[ee]);
                    const float* w = &WI[(e + ee) * XS + cb];
                    ulonglong2 Wa = *(const ulonglong2*)w;
                    ulonglong2 Wb = *(const ulonglong2*)(w + 4);
                    fma2(a0, Wa.x, d0); fma2(a1, Wa.y, d0);
                    fma2(a2, Wb.x, d0); fma2(a3, Wb.y, d0);
                    fma2(b0, Wa.x, d1); fma2(b1, Wa.y, d1);
                    fma2(b2, Wb.x, d1); fma2(b3, Wb.y, d1);
                }
            }
            if (v0) {
                ulonglong2 t0; t0.x = a0; t0.y = a1;
                ulonglong2 t1; t1.x = a2; t1.y = a3;
                *(ulonglong2*)&X[u0*XS + cb]     = t0;
                *(ulonglong2*)&X[u0*XS + cb + 4] = t1;
            }
            if (v1) {
                ulonglong2 t0; t0.x = b0; t0.y = b1;
                ulonglong2 t1; t1.x = b2; t1.y = b3;
                *(ulonglong2*)&X[u1*XS + cb]     = t0;
                *(ulonglong2*)&X[u1*XS + cb + 4] = t1;
            }
        }
    } else {
        stage(0, 0);        // layer 0 -> buf0
        stage(1, 1);        // layer 1 -> buf1
    }
    __syncthreads();

    // ================= 16 dilated layers =================================
    int W = 75;
    int cur = 0;            // li % 3
    #pragma unroll 1
    for (int li = 0; li < 16; li++) {
        const int d = 1 << (li & 3);
        if (li) W -= d + 1;

        float* WB  = sm + OFF_WB + cur * WBSZ;
        const float* WD  = WB + WDO;
        const float* WF  = WB + WFO;
        const float* WG  = WB + WGO;
        const float* WRs = WB + WRO;
        const float* BS  = WB + BSO;

        // staging warps: prefetch layer li+2 while compute runs
        if (warp >= 8 && li < 14) {
            int bi = cur + 2; if (bi >= 3) bi -= 3;
            stage(li + 2, bi);
        }

        // ---- dilated conv -> RB, u in [0, W] ----
        if (warp < 8 && 64 * pg <= W) {
            const int v0 = (u0 <= W), v1 = (u1 <= W);
            const int uu0 = v0 ? u0 : 0, uu1 = v1 ? u1 : 0;
            u64 a0 = pack2(BS[cb],   BS[cb+1]);
            u64 a1 = pack2(BS[cb+2], BS[cb+3]);
            u64 a2 = pack2(BS[cb+4], BS[cb+5]);
            u64 a3 = pack2(BS[cb+6], BS[cb+7]);
            u64 b0 = a0, b1 = a1, b2 = a2, b3 = a3;
            const float* p00 = &X[uu0*XS];
            const float* p01 = &X[(uu0 + d)*XS];
            const float* p10 = &X[uu1*XS];
            const float* p11 = &X[(uu1 + d)*XS];
            #pragma unroll 4
            for (int r = 0; r < 32; r += 4) {
                float4 xa0 = *(const float4*)(p00 + r);
                float4 xb0 = *(const float4*)(p01 + r);
                float4 xa1 = *(const float4*)(p10 + r);
                float4 xb1 = *(const float4*)(p11 + r);
                #pragma unroll
                for (int rr = 0; rr < 4; rr++) {
                    const float* w = &WD[(2*(r + rr))*XS + cb];
                    ulonglong2 Wa = *(const ulonglong2*)w;
                    ulonglong2 Wb = *(const ulonglong2*)(w + 4);
                    ulonglong2 Va = *(const ulonglong2*)(w + XS);
                    ulonglong2 Vb = *(const ulonglong2*)(w + XS + 4);
                    u64 d00 = dup2((&xa0.x)[rr]), d01 = dup2((&xb0.x)[rr]);
                    u64 d10 = dup2((&xa1.x)[rr]), d11 = dup2((&xb1.x)[rr]);
                    fma2(a0, Wa.x, d00); fma2(a1, Wa.y, d00);
                    fma2(a2, Wb.x, d00); fma2(a3, Wb.y, d00);
                    fma2(a0, Va.x, d01); fma2(a1, Va.y, d01);
                    fma2(a2, Vb.x, d01); fma2(a3, Vb.y, d01);
                    fma2(b0, Wa.x, d10); fma2(b1, Wa.y, d10);
                    fma2(b2, Wb.x, d10); fma2(b3, Wb.y, d10);
                    fma2(b0, Va.x, d11); fma2(b1, Va.y, d11);
                    fma2(b2, Vb.x, d11); fma2(b3, Vb.y, d11);
                }
            }
            if (v0) {
                ulonglong2 t0; t0.x = a0; t0.y = a1;
                ulonglong2 t1; t1.x = a2; t1.y = a3;
                *(ulonglong2*)&RB[u0*XS + cb]     = t0;
                *(ulonglong2*)&RB[u0*XS + cb + 4] = t1;
            }
            if (v1) {
                ulonglong2 t0; t0.x = b0; t0.y = b1;
                ulonglong2 t1; t1.x = b2; t1.y = b3;
                *(ulonglong2*)&RB[u1*XS + cb]     = t0;
                *(ulonglong2*)&RB[u1*XS + cb + 4] = t1;
            }
        }
        __syncthreads();

        // ---- filter & gate convs + activation + product -> GT, u in [0, W) ----
        if (warp < 8 && 64 * pg < W) {
            const int v0 = (u0 < W), v1 = (u1 < W);
            const int uu0 = v0 ? u0 : 0, uu1 = v1 ? u1 : 0;
            u64 f0 = pack2(BS[32+cb],   BS[32+cb+1]);
            u64 f1 = pack2(BS[32+cb+2], BS[32+cb+3]);
            u64 f2 = pack2(BS[32+cb+4], BS[32+cb+5]);
            u64 f3 = pack2(BS[32+cb+6], BS[32+cb+7]);
            u64 g0 = pack2(BS[64+cb],   BS[64+cb+1]);
            u64 g1 = pack2(BS[64+cb+2], BS[64+cb+3]);
            u64 g2 = pack2(BS[64+cb+4], BS[64+cb+5]);
            u64 g3 = pack2(BS[64+cb+6], BS[64+cb+7]);
            u64 h0 = f0, h1 = f1, h2 = f2, h3 = f3;   // pos1 filter
            u64 k0 = g0, k1 = g1, k2 = g2, k3 = g3;   // pos1 gate
            const float* p00 = &RB[uu0*XS];
            const float* p01 = &RB[(uu0 + 1)*XS];
            const float* p10 = &RB[uu1*XS];
            const float* p11 = &RB[(uu1 + 1)*XS];
            #pragma unroll 4
            for (int r = 0; r < 32; r += 4) {
                float4 xa0 = *(const float4*)(p00 + r);
                float4 xb0 = *(const float4*)(p01 + r);
                float4 xa1 = *(const float4*)(p10 + r);
                float4 xb1 = *(const float4*)(p11 + r);
                #pragma unroll
                for (int rr = 0; rr < 4; rr++) {
                    u64 d00 = dup2((&xa0.x)[rr]), d01 = dup2((&xb0.x)[rr]);
                    u64 d10 = dup2((&xa1.x)[rr]), d11 = dup2((&xb1.x)[rr]);
                    const float* wf = &WF[(2*(r + rr))*XS + cb];
                    ulonglong2 Fa = *(const ulonglong2*)wf;
                    ulonglong2 Fb = *(const ulonglong2*)(wf + 4);
                    ulonglong2 Fc = *(const ulonglong2*)(wf + XS);
                    ulonglong2 Fd = *(const ulonglong2*)(wf + XS + 4);
                    fma2(f0, Fa.x, d00); fma2(f1, Fa.y, d00);
                    fma2(f2, Fb.x, d00); fma2(f3, Fb.y, d00);
                    fma2(f0, Fc.x, d01); fma2(f1, Fc.y, d01);
                    fma2(f2, Fd.x, d01); fma2(f3, Fd.y, d01);
                    fma2(h0, Fa.x, d10); fma2(h1, Fa.y, d10);
                    fma2(h2, Fb.x, d10); fma2(h3, Fb.y, d10);
                    fma2(h0, Fc.x, d11); fma2(h1, Fc.y, d11);
                    fma2(h2, Fd.x, d11); fma2(h3, Fd.y, d11);
                    const float* wg = &WG[(2*(r + rr))*XS + cb];
                    ulonglong2 Ga = *(const ulonglong2*)wg;
                    ulonglong2 Gb = *(const ulonglong2*)(wg + 4);
                    ulonglong2 Gc = *(const ulonglong2*)(wg + XS);
                    ulonglong2 Gd = *(const ulonglong2*)(wg + XS + 4);
                    fma2(g0, Ga.x, d00); fma2(g1, Ga.y, d00);
                    fma2(g2, Gb.x, d00); fma2(g3, Gb.y, d00);
                    fma2(g0, Gc.x, d01); fma2(g1, Gc.y, d01);
                    fma2(g2, Gd.x, d01); fma2(g3, Gd.y, d01);
                    fma2(k0, Ga.x, d10); fma2(k1, Ga.y, d10);
                    fma2(k2, Gb.x, d10); fma2(k3, Gb.y, d10);
                    fma2(k0, Gc.x, d11); fma2(k1, Gc.y, d11);
                    fma2(k2, Gd.x, d11); fma2(k3, Gd.y, d11);
                }
            }
            if (v0) {
                float2 Fv[4] = {unpk(f0), unpk(f1), unpk(f2), unpk(f3)};
                float2 Gv[4] = {unpk(g0), unpk(g1), unpk(g2), unpk(g3)};
                float o[8];
                #pragma unroll
                for (int q = 0; q < 4; q++) {
                    o[2*q]   = fast_tanh(Fv[q].x) * fast_sig(Gv[q].x);
                    o[2*q+1] = fast_tanh(Fv[q].y) * fast_sig(Gv[q].y);
                }
                *(float4*)&GT[u0*XS + cb]     = make_float4(o[0], o[1], o[2], o[3]);
                *(float4*)&GT[u0*XS + cb + 4] = make_float4(o[4], o[5], o[6], o[7]);
            }
            if (v1) {
                float2 Fv[4] = {unpk(h0), unpk(h1), unpk(h2), unpk(h3)};
                float2 Gv[4] = {unpk(k0), unpk(k1), unpk(k2), unpk(k3)};
                float o[8];
                #pragma unroll
                for (int q = 0; q < 4; q++) {
                    o[2*q]   = fast_tanh(Fv[q].x) * fast_sig(Gv[q].x);
                    o[2*q+1] = fast_tanh(Fv[q].y) * fast_sig(Gv[q].y);
                }
                *(float4*)&GT[u1*XS + cb]     = make_float4(o[0], o[1], o[2], o[3]);
                *(float4*)&GT[u1*XS + cb + 4] = make_float4(o[4], o[5], o[6], o[7]);
            }
        }
        __syncthreads();

        // ---- res 1x1 conv + residual add -> X, u in [0, W) ----
        if (li < 15) {
            if (warp < 8 && 64 * pg < W) {
                const int v0 = (u0 < W), v1 = (u1 < W);
                const int uu0 = v0 ? u0 : 0, uu1 = v1 ? u1 : 0;
                u64 a0 = pack2(BS[96+cb],   BS[96+cb+1]);
                u64 a1 = pack2(BS[96+cb+2], BS[96+cb+3]);
                u64 a2 = pack2(BS[96+cb+4], BS[96+cb+5]);
                u64 a3 = pack2(BS[96+cb+6], BS[96+cb+7]);
                u64 b0 = a0, b1 = a1, b2 = a2, b3 = a3;
                const float* p0 = &GT[uu0*XS];
                const float* p1 = &GT[uu1*XS];
                #pragma unroll 4
                for (int r = 0; r < 32; r += 4) {
                    float4 xa0 = *(const float4*)(p0 + r);
                    float4 xa1 = *(const float4*)(p1 + r);
                    #pragma unroll
                    for (int rr = 0; rr < 4; rr++) {
                        u64 d0 = dup2((&xa0.x)[rr]);
                        u64 d1 = dup2((&xa1.x)[rr]);
                        const float* w = &WRs[(r + rr)*XS + cb];
                        ulonglong2 Wa = *(const ulonglong2*)w;
                        ulonglong2 Wb = *(const ulonglong2*)(w + 4);
                        fma2(a0, Wa.x, d0); fma2(a1, Wa.y, d0);
                        fma2(a2, Wb.x, d0); fma2(a3, Wb.y, d0);
                        fma2(b0, Wa.x, d1); fma2(b1, Wa.y, d1);
                        fma2(b2, Wb.x, d1); fma2(b3, Wb.y, d1);
                    }
                }
                if (v0) {
                    ulonglong2 r0 = *(const ulonglong2*)&RB[u0*XS + cb];
                    ulonglong2 r1 = *(const ulonglong2*)&RB[u0*XS + cb + 4];
                    ulonglong2 t0; t0.x = add2(a0, r0.x); t0.y = add2(a1, r0.y);
                    ulonglong2 t1; t1.x = add2(a2, r1.x); t1.y = add2(a3, r1.y);
                    *(ulonglong2*)&X[u0*XS + cb]     = t0;
                    *(ulonglong2*)&X[u0*XS + cb + 4] = t1;
                }
                if (v1) {
                    ulonglong2 r0 = *(const ulonglong2*)&RB[u1*XS + cb];
                    ulonglong2 r1 = *(const ulonglong2*)&RB[u1*XS + cb + 4];
                    ulonglong2 t0; t0.x = add2(b0, r0.x); t0.y = add2(b1, r0.y);
                    ulonglong2 t1; t1.x = add2(b2, r1.x); t1.y = add2(b3, r1.y);
                    *(ulonglong2*)&X[u1*XS + cb]     = t0;
                    *(ulonglong2*)&X[u1*XS + cb + 4] = t1;
                }
            }
            __syncthreads();
        }
        cur++; if (cur == 3) cur = 0;
    }

    // ================= tail: skip/end/fc at t = T-1 only =================
    float* SV = RB;        // relu(skip) 256
    float* H1 = RB + 256;  // 256
    float* H2 = RB + 512;  // 256
    float* F1 = RB + 768;  // 128
    float* F2 = RB + 896;  // 128
    float* F3 = RB + 1024; // 64

    const float* skw = skip_w + 15*256*32;
    const float* skb = skip_b + 15*256;
    float gv = GT[lane];
    #pragma unroll 2
    for (int o = warp; o < 256; o += 16) {
        float v = __ldg(&skw[o*32 + lane]) * gv;
        v = warp_sum(v);
        if (lane == 0) SV[o] = fmaxf(v + skb[o], 0.f);
    }
    __syncthreads();
    #pragma unroll 2
    for (int o = warp; o < 256; o += 16) {
        const float4* wp = (const float4*)(end1_w + o*256);
        const float4* sp = (const float4*)SV;
        float v = dot4(__ldg(wp + lane), sp[lane]) + dot4(__ldg(wp + lane + 32), sp[lane + 32]);
        v = warp_sum(v);
        if (lane == 0) H1[o] = fmaxf(v + end1_b[o], 0.f);
    }
    __syncthreads();
    #pragma unroll 2
    for (int o = warp; o < 256; o += 16) {
        const float4* wp = (const float4*)(end2_w + o*256);
        const float4* sp = (const float4*)H1;
        float v = dot4(__ldg(wp + lane), sp[lane]) + dot4(__ldg(wp + lane + 32), sp[lane + 32]);
        v = warp_sum(v);
        if (lane == 0) H2[o] = v + end2_b[o];
    }
    __syncthreads();
    #pragma unroll 2
    for (int o = warp; o < 128; o += 16) {
        const float4* wp = (const float4*)(fc1_w + o*256);
        const float4* sp = (const float4*)H2;
        float v = dot4(__ldg(wp + lane), sp[lane]) + dot4(__ldg(wp + lane + 32), sp[lane + 32]);
        v = warp_sum(v);
        if (lane == 0) F1[o] = fmaxf(v + fc1_b[o], 0.f);
    }
    __syncthreads();
    #pragma unroll 2
    for (int o = warp; o < 128; o += 16) {
        const float4* wp = (const float4*)(fc2_w + o*128);
        const float4* sp = (const float4*)F1;
        float v = dot4(__ldg(wp + lane), sp[lane]);
        v = warp_sum(v);
        if (lane == 0) F2[o] = fmaxf(v + fc2_b[o], 0.f);
    }
    __syncthreads();
    #pragma unroll 2
    for (int o = warp; o < 64; o += 16) {
        const float4* wp = (const float4*)(fc3_w + o*128);
        const float4* sp = (const float4*)F2;
        float v = dot4(__ldg(wp + lane), sp[lane]);
        v = warp_sum(v);
        if (lane == 0) F3[o] = fmaxf(v + fc3_b[o], 0.f);
    }
    __syncthreads();
    #pragma unroll 2
    for (int o = warp; o < 256; o += 16) {
        const float2* wp = (const float2*)(fc4_w + o*64);
        const float2* sp = (const float2*)F3;
        float2 wv = __ldg(wp + lane);
        float2 sv = sp[lane];
        float v = fmaf(wv.x, sv.x, wv.y * sv.y);
        v = warp_sum(v);
        if (lane == 0) out[b*256 + o] = v + fc4_b[o];
    }
}

extern "C" void kernel_launch(void* const* d_in, const int* in_sizes, int n_in,
                              void* d_out, int out_size)
{
    (void)in_sizes; (void)n_in; (void)out_size;
    const size_t smem_bytes = (size_t)SMEM_FLOATS * sizeof(float);
    cudaFuncSetAttribute(wavenet_kernel, cudaFuncAttributeMaxDynamicSharedMemorySize,
                         (int)smem_bytes);
    wavenet_kernel<<<16, NT, smem_bytes>>>(
        (const int*)  d_in[0],  (const float*)d_in[1],
        (const float*)d_in[2],  (const float*)d_in[3],
        (const float*)d_in[4],  (const float*)d_in[5],
        (const float*)d_in[6],  (const float*)d_in[7],
        (const float*)d_in[8],  (const float*)d_in[9],
        (const float*)d_in[10], (const float*)d_in[11],
        (const float*)d_in[12], (const float*)d_in[13],
        (const float*)d_in[14], (const float*)d_in[15],
        (const float*)d_in[16], (const float*)d_in[17],
        (const float*)d_in[18], (const float*)d_in[19],
        (const float*)d_in[20], (const float*)d_in[21],
        (const float*)d_in[22], (const float*)d_in[23],
        (const float*)d_in[24], (const float*)d_in[25],
        (float*)d_out);
}